// round 6
// baseline (speedup 1.0000x reference)
#include <cuda_runtime.h>
#include <math.h>

#define NN 20000
#define NE 5000
#define NZ 160000
#define DD 128
#define EPS_F 1e-10f
#define ALPHA_F 0.2f

// ---------------- scratch (static device globals; no allocation) -------------
__device__ __align__(16) float g_Xp[NN * DD];     // X @ W
__device__ __align__(16) float g_E2[NE * DD];     // edge features after de_inv
__device__ __align__(16) float g_ef[NE * DD];     // final edge_feats
__device__ __align__(16) float g_Sbase[DD];
__device__ float g_dv[NN];
__device__ float g_de[NE];
__device__ float g_dvinv[NN];
__device__ float g_b[NN];
__device__ float g_s1[NN];
__device__ float g_s2[NN];
__device__ int   g_cnt_row[NN];
__device__ int   g_cnt_col[NE];
__device__ int   g_row_ptr[NN + 1];
__device__ int   g_col_ptr[NE + 1];
__device__ int   g_cur_row[NN];
__device__ int   g_cur_col[NE];
__device__ int   g_row_ent[NZ];
__device__ int   g_col_ent[NZ];
__device__ float g_coef[NZ];

// ---------------- zero scratch ----------------
__global__ void k_zero() {
    int i = blockIdx.x * blockDim.x + threadIdx.x;
    int stride = gridDim.x * blockDim.x;
    for (int t = i; t < NN; t += stride) { g_cnt_row[t] = 0; g_dv[t] = 0.f; }
    for (int t = i; t < NE; t += stride) { g_cnt_col[t] = 0; g_de[t] = 0.f; }
    for (int t = i; t < DD; t += stride) g_Sbase[t] = 0.f;
}

// ---------------- degree + count histogram ----------------
__global__ void k_hist(const int* __restrict__ rows, const int* __restrict__ cols,
                       const float* __restrict__ vals) {
    int k = blockIdx.x * blockDim.x + threadIdx.x;
    if (k >= NZ) return;
    int r = rows[k], c = cols[k];
    float v = vals[k];
    atomicAdd(&g_dv[r], v);
    atomicAdd(&g_de[c], v);
    atomicAdd(&g_cnt_row[r], 1);
    atomicAdd(&g_cnt_col[c], 1);
}

// ---------------- exclusive scan (block 0: rows, block 1: cols) -------------
__global__ void k_scan() {
    bool isrow = (blockIdx.x == 0);
    int n = isrow ? NN : NE;
    int* cnt = isrow ? g_cnt_row : g_cnt_col;
    int* ptr = isrow ? g_row_ptr : g_col_ptr;
    int* cur = isrow ? g_cur_row : g_cur_col;
    __shared__ int wsum[32];
    __shared__ int carry;
    int lane = threadIdx.x & 31, wid = threadIdx.x >> 5;
    if (threadIdx.x == 0) carry = 0;
    __syncthreads();
    for (int base = 0; base < n; base += blockDim.x) {
        int i = base + threadIdx.x;
        int v = (i < n) ? cnt[i] : 0;
        int s = v;
#pragma unroll
        for (int d = 1; d < 32; d <<= 1) {
            int t = __shfl_up_sync(0xffffffffu, s, d);
            if (lane >= d) s += t;
        }
        if (lane == 31) wsum[wid] = s;
        __syncthreads();
        if (wid == 0) {
            int ws = wsum[lane];
            int ss = ws;
#pragma unroll
            for (int d = 1; d < 32; d <<= 1) {
                int t = __shfl_up_sync(0xffffffffu, ss, d);
                if (lane >= d) ss += t;
            }
            wsum[lane] = ss - ws;  // exclusive warp offset
        }
        __syncthreads();
        int ex = carry + wsum[wid] + (s - v);
        if (i < n) { ptr[i] = ex; cur[i] = ex; }
        if (isrow && i < n) g_dvinv[i] = rsqrtf(g_dv[i] + EPS_F);
        __syncthreads();
        if (threadIdx.x == blockDim.x - 1) carry = ex + v;
        __syncthreads();
    }
    if (threadIdx.x == 0) ptr[n] = carry;
}

// ---------------- fill CSR entry lists ----------------
__global__ void k_fill(const int* __restrict__ rows, const int* __restrict__ cols) {
    int k = blockIdx.x * blockDim.x + threadIdx.x;
    if (k >= NZ) return;
    int r = rows[k];
    int p = atomicAdd(&g_cur_row[r], 1);
    g_row_ent[p] = k;
    int c = cols[k];
    int q = atomicAdd(&g_cur_col[c], 1);
    g_col_ent[q] = k;
}

// ---------------- X_proj = x @ W  (128x128 tile, 8x8 register tiles) --------
#define BM 128
#define BN 128
#define BK 16
__global__ __launch_bounds__(256) void k_gemm(const float* __restrict__ A,
                                              const float* __restrict__ B) {
    __shared__ __align__(16) float As[BK][BM];
    __shared__ __align__(16) float Bs[BK][BN];
    int tid = threadIdx.x;
    int row0 = blockIdx.x * BM;
    int tr = (tid >> 4) << 3;
    int tc = (tid & 15) << 3;
    float acc[8][8];
#pragma unroll
    for (int i = 0; i < 8; i++)
#pragma unroll
        for (int j = 0; j < 8; j++) acc[i][j] = 0.f;

    for (int k0 = 0; k0 < DD; k0 += BK) {
#pragma unroll
        for (int t = 0; t < 2; t++) {
            int slot = t * 256 + tid;              // 0..511
            // A tile: 128 rows x 16 k, 512 float4 slots
            int ar = slot >> 2, aq = slot & 3;
            float4 va = make_float4(0.f, 0.f, 0.f, 0.f);
            int grow = row0 + ar;
            if (grow < NN) va = *(const float4*)(A + grow * DD + k0 + aq * 4);
            As[aq * 4 + 0][ar] = va.x;
            As[aq * 4 + 1][ar] = va.y;
            As[aq * 4 + 2][ar] = va.z;
            As[aq * 4 + 3][ar] = va.w;
            // B tile: 16 k x 128 cols
            int brow = slot >> 5, bq = slot & 31;
            *(float4*)(&Bs[brow][bq * 4]) = *(const float4*)(B + (k0 + brow) * DD + bq * 4);
        }
        __syncthreads();
#pragma unroll
        for (int kk = 0; kk < BK; kk++) {
            float av[8], bv[8];
            *(float4*)(av)     = *(const float4*)(&As[kk][tr]);
            *(float4*)(av + 4) = *(const float4*)(&As[kk][tr + 4]);
            *(float4*)(bv)     = *(const float4*)(&Bs[kk][tc]);
            *(float4*)(bv + 4) = *(const float4*)(&Bs[kk][tc + 4]);
#pragma unroll
            for (int i = 0; i < 8; i++)
#pragma unroll
                for (int j = 0; j < 8; j++) acc[i][j] = fmaf(av[i], bv[j], acc[i][j]);
        }
        __syncthreads();
    }
#pragma unroll
    for (int i = 0; i < 8; i++) {
        int grow = row0 + tr + i;
        if (grow < NN) {
            *(float4*)(&g_Xp[grow * DD + tc])     = make_float4(acc[i][0], acc[i][1], acc[i][2], acc[i][3]);
            *(float4*)(&g_Xp[grow * DD + tc + 4]) = make_float4(acc[i][4], acc[i][5], acc[i][6], acc[i][7]);
        }
    }
}

// ---------------- E2[c] = de_inv[c] * sum vals*dvinv[r]*Xp[r]  (warp/edge) --
__global__ void k_e2(const int* __restrict__ rows, const float* __restrict__ vals) {
    int gw = (blockIdx.x * blockDim.x + threadIdx.x) >> 5;
    if (gw >= NE) return;
    int lane = threadIdx.x & 31;
    int s = g_col_ptr[gw], e = g_col_ptr[gw + 1];
    float4 acc = make_float4(0.f, 0.f, 0.f, 0.f);
    for (int j = s; j < e; j++) {
        int k = g_col_ent[j];
        int r = rows[k];
        float w = vals[k] * g_dvinv[r];
        float4 xv = ((const float4*)(g_Xp + r * DD))[lane];
        acc.x += w * xv.x; acc.y += w * xv.y; acc.z += w * xv.z; acc.w += w * xv.w;
    }
    float dei = 1.f / (g_de[gw] + EPS_F);
    ((float4*)(g_E2 + gw * DD))[lane] =
        make_float4(acc.x * dei, acc.y * dei, acc.z * dei, acc.w * dei);
}

// ---------------- Y_hat (in regs) -> s1, s2   (warp/row) --------------------
__global__ void k_yhat(const int* __restrict__ cols, const float* __restrict__ vals,
                       const float* __restrict__ a) {
    int gw = (blockIdx.x * blockDim.x + threadIdx.x) >> 5;
    if (gw >= NN) return;
    int lane = threadIdx.x & 31;
    int s = g_row_ptr[gw], e = g_row_ptr[gw + 1];
    float4 acc = make_float4(0.f, 0.f, 0.f, 0.f);
    for (int j = s; j < e; j++) {
        int k = g_row_ent[j];
        int c = cols[k];
        float w = vals[k];
        float4 ev = ((const float4*)(g_E2 + c * DD))[lane];
        acc.x += w * ev.x; acc.y += w * ev.y; acc.z += w * ev.z; acc.w += w * ev.w;
    }
    float dvi = g_dvinv[gw];
    float4 xp = ((const float4*)(g_Xp + gw * DD))[lane];
    float4 y = make_float4(acc.x * dvi + xp.x, acc.y * dvi + xp.y,
                           acc.z * dvi + xp.z, acc.w * dvi + xp.w);
    float4 a1 = ((const float4*)a)[lane];
    float4 a2 = ((const float4*)(a + DD))[lane];
    float p1 = y.x * a1.x + y.y * a1.y + y.z * a1.z + y.w * a1.w;
    float p2 = y.x * a2.x + y.y * a2.y + y.z * a2.z + y.w * a2.w;
#pragma unroll
    for (int o = 16; o > 0; o >>= 1) {
        p1 += __shfl_xor_sync(0xffffffffu, p1, o);
        p2 += __shfl_xor_sync(0xffffffffu, p2, o);
    }
    if (lane == 0) { g_s1[gw] = p1; g_s2[gw] = p2; }
}

// ---------------- per-row softmax stats + per-pair coefficients -------------
// Handles duplicate (r,c) pairs exactly: duplicates share the same logit e,
// so the deduped value is v = occ * e. coef[k] = exp(v-m)/Z - b on one
// representative entry per distinct pair; 0 on duplicates.
__global__ void k_attn(const int* __restrict__ cols) {
    int r = blockIdx.x * blockDim.x + threadIdx.x;
    if (r >= NN) return;
    int s = g_row_ptr[r], e = g_row_ptr[r + 1];
    int n = e - s;
    float s1r = g_s1[r];
    const int CAP = 64;
    int lc[CAP];
    int lk[CAP];
    int ncache = n < CAP ? n : CAP;
    for (int j = 0; j < ncache; j++) {
        int k = g_row_ent[s + j];
        lk[j] = k;
        lc[j] = cols[k];
    }
    const float NEGINF = -INFINITY;
    float m = 0.f;
    int cnt = 0;
    for (int j = 0; j < n; j++) {
        int kj = (j < CAP) ? lk[j] : g_row_ent[s + j];
        int cj = (j < CAP) ? lc[j] : cols[kj];
        bool dup = false;
        for (int i = 0; i < j; i++) {
            int ci = (i < CAP) ? lc[i] : cols[g_row_ent[s + i]];
            if (ci == cj) { dup = true; break; }
        }
        if (dup) { g_coef[kj] = NEGINF; continue; }
        int occ = 1;
        for (int i = j + 1; i < n; i++) {
            int ci = (i < CAP) ? lc[i] : cols[g_row_ent[s + i]];
            if (ci == cj) occ++;
        }
        float z = s1r + g_s2[cj];
        float ev = (z > 0.f) ? z : ALPHA_F * z;
        float v = (float)occ * ev;
        g_coef[kj] = v;
        if (v > m) m = v;
        cnt++;
    }
    float Z = (float)(NE - cnt) * __expf(-m);
    for (int j = 0; j < n; j++) {
        int kj = (j < CAP) ? lk[j] : g_row_ent[s + j];
        float v = g_coef[kj];
        if (v != NEGINF) Z += __expf(v - m);
    }
    float b = __expf(-m) / Z;
    g_b[r] = b;
    for (int j = 0; j < n; j++) {
        int kj = (j < CAP) ? lk[j] : g_row_ent[s + j];
        float v = g_coef[kj];
        g_coef[kj] = (v == NEGINF) ? 0.f : (__expf(v - m) / Z - b);
    }
}

// ---------------- S_base[d] = sum_r b_r * Xp[r][d] ----------------
__global__ void k_sbase() {
    int d = threadIdx.x;  // 128 threads
    int r0 = blockIdx.x * 128;
    int r1 = r0 + 128;
    if (r1 > NN) r1 = NN;
    float p = 0.f;
    for (int r = r0; r < r1; r++) p += g_b[r] * g_Xp[r * DD + d];
    atomicAdd(&g_Sbase[d], p);
}

// ---------------- edge_feats[c] = S_base + sum coef*Xp[r]  (warp/edge) ------
__global__ void k_edge(const int* __restrict__ rows) {
    int gw = (blockIdx.x * blockDim.x + threadIdx.x) >> 5;
    if (gw >= NE) return;
    int lane = threadIdx.x & 31;
    int s = g_col_ptr[gw], e = g_col_ptr[gw + 1];
    float4 acc = ((const float4*)g_Sbase)[lane];
    for (int j = s; j < e; j++) {
        int k = g_col_ent[j];
        float cf = g_coef[k];
        if (cf != 0.f) {
            int r = rows[k];
            float4 xv = ((const float4*)(g_Xp + r * DD))[lane];
            acc.x += cf * xv.x; acc.y += cf * xv.y; acc.z += cf * xv.z; acc.w += cf * xv.w;
        }
    }
    ((float4*)(g_ef + gw * DD))[lane] = acc;
}

// ---------------- out[r] = bias + sum vals*edge_feats[c]  (warp/row) --------
__global__ void k_out(const int* __restrict__ cols, const float* __restrict__ vals,
                      const float* __restrict__ bias, float* __restrict__ out) {
    int gw = (blockIdx.x * blockDim.x + threadIdx.x) >> 5;
    if (gw >= NN) return;
    int lane = threadIdx.x & 31;
    int s = g_row_ptr[gw], e = g_row_ptr[gw + 1];
    float4 acc = ((const float4*)bias)[lane];
    for (int j = s; j < e; j++) {
        int k = g_row_ent[j];
        int c = cols[k];
        float w = vals[k];
        float4 ev = ((const float4*)(g_ef + c * DD))[lane];
        acc.x += w * ev.x; acc.y += w * ev.y; acc.z += w * ev.z; acc.w += w * ev.w;
    }
    ((float4*)(out + gw * DD))[lane] = acc;
}

// ---------------- launcher ----------------
extern "C" void kernel_launch(void* const* d_in, const int* in_sizes, int n_in,
                              void* d_out, int out_size) {
    const float* x    = (const float*)d_in[0];
    const int*   rows = (const int*)d_in[1];
    const int*   cols = (const int*)d_in[2];
    const float* vals = (const float*)d_in[3];
    const float* W    = (const float*)d_in[4];
    const float* a    = (const float*)d_in[5];
    const float* bias = (const float*)d_in[6];
    float* out = (float*)d_out;

    k_zero<<<80, 256>>>();
    k_hist<<<(NZ + 255) / 256, 256>>>(rows, cols, vals);
    k_scan<<<2, 1024>>>();
    k_fill<<<(NZ + 255) / 256, 256>>>(rows, cols);
    k_gemm<<<(NN + BM - 1) / BM, 256>>>(x, W);
    k_e2<<<(NE * 32 + 255) / 256, 256>>>(rows, vals);
    k_yhat<<<(NN * 32 + 255) / 256, 256>>>(cols, vals, a);
    k_attn<<<(NN + 255) / 256, 256>>>(cols);
    k_sbase<<<(NN + 127) / 128, 128>>>();
    k_edge<<<(NE * 32 + 255) / 256, 256>>>(rows);
    k_out<<<(NN * 32 + 255) / 256, 256>>>(cols, vals, bias, out);
}

// round 9
// speedup vs baseline: 1.2335x; 1.2335x over previous
#include <cuda_runtime.h>
#include <math.h>

#define NN 20000
#define NE 5000
#define NZ 160000
#define DD 128
#define EPS_F 1e-10f
#define ALPHA_F 0.2f

#define SB 256
#define NBR ((NN + SB - 1) / SB)   // 79
#define NBC ((NE + SB - 1) / SB)   // 20

// ---------------- scratch (static device globals; no allocation) -------------
__device__ __align__(16) float g_Xp[NN * DD];     // X @ W
__device__ __align__(16) float g_E2[NE * DD];     // edge features after de_inv
__device__ __align__(16) float g_ef[NE * DD];     // final edge_feats
__device__ __align__(16) float g_Sbase[DD];
__device__ float g_dv[NN];
__device__ float g_de[NE];
__device__ float g_dvinv[NN];
__device__ float g_b[NN];
__device__ float g_s1[NN];
__device__ float g_s2[NN];
__device__ int   g_cnt_row[NN];
__device__ int   g_cnt_col[NE];
__device__ int   g_row_ptr[NN + 1];
__device__ int   g_col_ptr[NE + 1];
__device__ int   g_cur_row[NN];
__device__ int   g_cur_col[NE];
__device__ int   g_row_ent[NZ];
__device__ int   g_col_ent[NZ];
__device__ float g_coef[NZ];
__device__ int   g_blksum[NBR + NBC];

// ---------------- zero scratch ----------------
__global__ void k_zero() {
    int i = blockIdx.x * blockDim.x + threadIdx.x;
    int stride = gridDim.x * blockDim.x;
    for (int t = i; t < NN; t += stride) { g_cnt_row[t] = 0; g_dv[t] = 0.f; }
    for (int t = i; t < NE; t += stride) { g_cnt_col[t] = 0; g_de[t] = 0.f; }
    for (int t = i; t < DD; t += stride) g_Sbase[t] = 0.f;
}

// ---------------- degree + count histogram (4 elems/thread for MLP) ---------
__global__ void k_hist(const int* __restrict__ rows, const int* __restrict__ cols,
                       const float* __restrict__ vals) {
    int t = blockIdx.x * blockDim.x + threadIdx.x;
    int k0 = t * 4;
    if (k0 >= NZ) return;
    int r[4], c[4];
    float v[4];
#pragma unroll
    for (int u = 0; u < 4; u++) {
        r[u] = rows[k0 + u];
        c[u] = cols[k0 + u];
        v[u] = vals[k0 + u];
    }
#pragma unroll
    for (int u = 0; u < 4; u++) atomicAdd(&g_dv[r[u]], v[u]);
#pragma unroll
    for (int u = 0; u < 4; u++) atomicAdd(&g_de[c[u]], v[u]);
#pragma unroll
    for (int u = 0; u < 4; u++) atomicAdd(&g_cnt_row[r[u]], 1);
#pragma unroll
    for (int u = 0; u < 4; u++) atomicAdd(&g_cnt_col[c[u]], 1);
}

// ---------------- hierarchical exclusive scan, stage 1 (block-local) --------
__global__ void k_scan1() {
    bool isrow = blockIdx.x < NBR;
    int bi = isrow ? blockIdx.x : blockIdx.x - NBR;
    int n = isrow ? NN : NE;
    const int* cnt = isrow ? g_cnt_row : g_cnt_col;
    int* ptr = isrow ? g_row_ptr : g_col_ptr;
    int i = bi * SB + threadIdx.x;
    int lane = threadIdx.x & 31, wid = threadIdx.x >> 5;
    int v = (i < n) ? cnt[i] : 0;
    int s = v;
#pragma unroll
    for (int d = 1; d < 32; d <<= 1) {
        int t = __shfl_up_sync(0xffffffffu, s, d);
        if (lane >= d) s += t;
    }
    __shared__ int ws[8];
    if (lane == 31) ws[wid] = s;
    __syncthreads();
    if (threadIdx.x < 8) {
        int wv = ws[threadIdx.x];
        int wss = wv;
#pragma unroll
        for (int d = 1; d < 8; d <<= 1) {
            int t = __shfl_up_sync(0xffu, wss, d);
            if (threadIdx.x >= d) wss += t;
        }
        ws[threadIdx.x] = wss - wv;  // exclusive warp offset
    }
    __syncthreads();
    int ex = ws[wid] + (s - v);
    if (i < n) ptr[i] = ex;
    if (threadIdx.x == SB - 1) g_blksum[blockIdx.x] = ex + v;
}

// ---------------- stage 2: scan block sums (1 block, 2 warps) ----------------
__global__ void k_scan2() {
    int wid = threadIdx.x >> 5, lane = threadIdx.x & 31;
    if (wid == 0) {
        int carry = 0;
        for (int b0 = 0; b0 < NBR; b0 += 32) {
            int idx = b0 + lane;
            int v = (idx < NBR) ? g_blksum[idx] : 0;
            int s = v;
#pragma unroll
            for (int d = 1; d < 32; d <<= 1) {
                int t = __shfl_up_sync(0xffffffffu, s, d);
                if (lane >= d) s += t;
            }
            if (idx < NBR) g_blksum[idx] = carry + s - v;
            carry += __shfl_sync(0xffffffffu, s, 31);
        }
        if (lane == 0) g_row_ptr[NN] = carry;
    } else if (wid == 1) {
        int carry = 0;
        for (int b0 = 0; b0 < NBC; b0 += 32) {
            int idx = b0 + lane;
            int v = (idx < NBC) ? g_blksum[NBR + idx] : 0;
            int s = v;
#pragma unroll
            for (int d = 1; d < 32; d <<= 1) {
                int t = __shfl_up_sync(0xffffffffu, s, d);
                if (lane >= d) s += t;
            }
            if (idx < NBC) g_blksum[NBR + idx] = carry + s - v;
            carry += __shfl_sync(0xffffffffu, s, 31);
        }
        if (lane == 0) g_col_ptr[NE] = carry;
    }
}

// ---------------- stage 3: add block offsets + dvinv -------------------------
__global__ void k_scan3() {
    bool isrow = blockIdx.x < NBR;
    int bi = isrow ? blockIdx.x : blockIdx.x - NBR;
    int n = isrow ? NN : NE;
    int* ptr = isrow ? g_row_ptr : g_col_ptr;
    int* cur = isrow ? g_cur_row : g_cur_col;
    int i = bi * SB + threadIdx.x;
    if (i < n) {
        int p = ptr[i] + g_blksum[blockIdx.x];
        ptr[i] = p;
        cur[i] = p;
        if (isrow) g_dvinv[i] = rsqrtf(g_dv[i] + EPS_F);
    }
}

// ---------------- fill CSR entry lists (4 elems/thread for MLP) --------------
__global__ void k_fill(const int* __restrict__ rows, const int* __restrict__ cols) {
    int t = blockIdx.x * blockDim.x + threadIdx.x;
    int k0 = t * 4;
    if (k0 >= NZ) return;
    int r[4], c[4];
#pragma unroll
    for (int u = 0; u < 4; u++) { r[u] = rows[k0 + u]; c[u] = cols[k0 + u]; }
    int p[4], q[4];
#pragma unroll
    for (int u = 0; u < 4; u++) p[u] = atomicAdd(&g_cur_row[r[u]], 1);
#pragma unroll
    for (int u = 0; u < 4; u++) q[u] = atomicAdd(&g_cur_col[c[u]], 1);
#pragma unroll
    for (int u = 0; u < 4; u++) g_row_ent[p[u]] = k0 + u;
#pragma unroll
    for (int u = 0; u < 4; u++) g_col_ent[q[u]] = k0 + u;
}

// ---------------- X_proj = x @ W  (128x128 tile, 8x8 register tiles) --------
#define BM 128
#define BN 128
#define BK 16
__global__ __launch_bounds__(256) void k_gemm(const float* __restrict__ A,
                                              const float* __restrict__ B) {
    __shared__ __align__(16) float As[BK][BM];
    __shared__ __align__(16) float Bs[BK][BN];
    int tid = threadIdx.x;
    int row0 = blockIdx.x * BM;
    int tr = (tid >> 4) << 3;
    int tc = (tid & 15) << 3;
    float acc[8][8];
#pragma unroll
    for (int i = 0; i < 8; i++)
#pragma unroll
        for (int j = 0; j < 8; j++) acc[i][j] = 0.f;

    for (int k0 = 0; k0 < DD; k0 += BK) {
#pragma unroll
        for (int t = 0; t < 2; t++) {
            int slot = t * 256 + tid;              // 0..511
            int ar = slot >> 2, aq = slot & 3;
            float4 va = make_float4(0.f, 0.f, 0.f, 0.f);
            int grow = row0 + ar;
            if (grow < NN) va = *(const float4*)(A + grow * DD + k0 + aq * 4);
            As[aq * 4 + 0][ar] = va.x;
            As[aq * 4 + 1][ar] = va.y;
            As[aq * 4 + 2][ar] = va.z;
            As[aq * 4 + 3][ar] = va.w;
            int brow = slot >> 5, bq = slot & 31;
            *(float4*)(&Bs[brow][bq * 4]) = *(const float4*)(B + (k0 + brow) * DD + bq * 4);
        }
        __syncthreads();
#pragma unroll
        for (int kk = 0; kk < BK; kk++) {
            float av[8], bv[8];
            *(float4*)(av)     = *(const float4*)(&As[kk][tr]);
            *(float4*)(av + 4) = *(const float4*)(&As[kk][tr + 4]);
            *(float4*)(bv)     = *(const float4*)(&Bs[kk][tc]);
            *(float4*)(bv + 4) = *(const float4*)(&Bs[kk][tc + 4]);
#pragma unroll
            for (int i = 0; i < 8; i++)
#pragma unroll
                for (int j = 0; j < 8; j++) acc[i][j] = fmaf(av[i], bv[j], acc[i][j]);
        }
        __syncthreads();
    }
#pragma unroll
    for (int i = 0; i < 8; i++) {
        int grow = row0 + tr + i;
        if (grow < NN) {
            *(float4*)(&g_Xp[grow * DD + tc])     = make_float4(acc[i][0], acc[i][1], acc[i][2], acc[i][3]);
            *(float4*)(&g_Xp[grow * DD + tc + 4]) = make_float4(acc[i][4], acc[i][5], acc[i][6], acc[i][7]);
        }
    }
}

// ---------------- E2[c]: warp/edge, lane-parallel index prefetch ------------
__global__ void k_e2(const int* __restrict__ rows, const float* __restrict__ vals) {
    int gw = (blockIdx.x * blockDim.x + threadIdx.x) >> 5;
    if (gw >= NE) return;
    int lane = threadIdx.x & 31;
    int s = g_col_ptr[gw], e = g_col_ptr[gw + 1];
    float4 acc = make_float4(0.f, 0.f, 0.f, 0.f);
    for (int j0 = s; j0 < e; j0 += 32) {
        int myj = j0 + lane;
        int rr = 0; float ww = 0.f;
        if (myj < e) {
            int k = g_col_ent[myj];
            rr = rows[k];
            ww = vals[k] * g_dvinv[rr];
        }
        int cnt = min(32, e - j0);
        for (int t = 0; t < cnt; t++) {
            int r2 = __shfl_sync(0xffffffffu, rr, t);
            float w2 = __shfl_sync(0xffffffffu, ww, t);
            float4 xv = ((const float4*)(g_Xp + r2 * DD))[lane];
            acc.x += w2 * xv.x; acc.y += w2 * xv.y;
            acc.z += w2 * xv.z; acc.w += w2 * xv.w;
        }
    }
    float dei = 1.f / (g_de[gw] + EPS_F);
    ((float4*)(g_E2 + gw * DD))[lane] =
        make_float4(acc.x * dei, acc.y * dei, acc.z * dei, acc.w * dei);
}

// ---------------- Y_hat -> s1, s2: warp/row, lane-parallel prefetch ---------
__global__ void k_yhat(const int* __restrict__ cols, const float* __restrict__ vals,
                       const float* __restrict__ a) {
    int gw = (blockIdx.x * blockDim.x + threadIdx.x) >> 5;
    if (gw >= NN) return;
    int lane = threadIdx.x & 31;
    int s = g_row_ptr[gw], e = g_row_ptr[gw + 1];
    float4 acc = make_float4(0.f, 0.f, 0.f, 0.f);
    for (int j0 = s; j0 < e; j0 += 32) {
        int myj = j0 + lane;
        int cc = 0; float ww = 0.f;
        if (myj < e) {
            int k = g_row_ent[myj];
            cc = cols[k];
            ww = vals[k];
        }
        int cnt = min(32, e - j0);
        for (int t = 0; t < cnt; t++) {
            int c2 = __shfl_sync(0xffffffffu, cc, t);
            float w2 = __shfl_sync(0xffffffffu, ww, t);
            float4 ev = ((const float4*)(g_E2 + c2 * DD))[lane];
            acc.x += w2 * ev.x; acc.y += w2 * ev.y;
            acc.z += w2 * ev.z; acc.w += w2 * ev.w;
        }
    }
    float dvi = g_dvinv[gw];
    float4 xp = ((const float4*)(g_Xp + gw * DD))[lane];
    float4 y = make_float4(acc.x * dvi + xp.x, acc.y * dvi + xp.y,
                           acc.z * dvi + xp.z, acc.w * dvi + xp.w);
    float4 a1 = ((const float4*)a)[lane];
    float4 a2 = ((const float4*)(a + DD))[lane];
    float p1 = y.x * a1.x + y.y * a1.y + y.z * a1.z + y.w * a1.w;
    float p2 = y.x * a2.x + y.y * a2.y + y.z * a2.z + y.w * a2.w;
#pragma unroll
    for (int o = 16; o > 0; o >>= 1) {
        p1 += __shfl_xor_sync(0xffffffffu, p1, o);
        p2 += __shfl_xor_sync(0xffffffffu, p2, o);
    }
    if (lane == 0) { g_s1[gw] = p1; g_s2[gw] = p2; }
}

// ---------------- per-row softmax stats + per-pair coefficients -------------
__global__ void k_attn(const int* __restrict__ cols) {
    int r = blockIdx.x * blockDim.x + threadIdx.x;
    if (r >= NN) return;
    int s = g_row_ptr[r], e = g_row_ptr[r + 1];
    int n = e - s;
    float s1r = g_s1[r];
    const int CAP = 64;
    int lc[CAP];
    int lk[CAP];
    int ncache = n < CAP ? n : CAP;
    for (int j = 0; j < ncache; j++) {
        int k = g_row_ent[s + j];
        lk[j] = k;
        lc[j] = cols[k];
    }
    const float NEGINF = -INFINITY;
    float m = 0.f;
    int cnt = 0;
    for (int j = 0; j < n; j++) {
        int kj = (j < CAP) ? lk[j] : g_row_ent[s + j];
        int cj = (j < CAP) ? lc[j] : cols[kj];
        bool dup = false;
        for (int i = 0; i < j; i++) {
            int ci = (i < CAP) ? lc[i] : cols[g_row_ent[s + i]];
            if (ci == cj) { dup = true; break; }
        }
        if (dup) { g_coef[kj] = NEGINF; continue; }
        int occ = 1;
        for (int i = j + 1; i < n; i++) {
            int ci = (i < CAP) ? lc[i] : cols[g_row_ent[s + i]];
            if (ci == cj) occ++;
        }
        float z = s1r + g_s2[cj];
        float ev = (z > 0.f) ? z : ALPHA_F * z;
        float v = (float)occ * ev;
        g_coef[kj] = v;
        if (v > m) m = v;
        cnt++;
    }
    float Z = (float)(NE - cnt) * __expf(-m);
    for (int j = 0; j < n; j++) {
        int kj = (j < CAP) ? lk[j] : g_row_ent[s + j];
        float v = g_coef[kj];
        if (v != NEGINF) Z += __expf(v - m);
    }
    float b = __expf(-m) / Z;
    g_b[r] = b;
    for (int j = 0; j < n; j++) {
        int kj = (j < CAP) ? lk[j] : g_row_ent[s + j];
        float v = g_coef[kj];
        g_coef[kj] = (v == NEGINF) ? 0.f : (__expf(v - m) / Z - b);
    }
}

// ---------------- S_base[d] = sum_r b_r * Xp[r][d] ----------------
__global__ void k_sbase() {
    int d = threadIdx.x;  // 128 threads
    int r0 = blockIdx.x * 128;
    int r1 = r0 + 128;
    if (r1 > NN) r1 = NN;
    float p = 0.f;
    for (int r = r0; r < r1; r++) p += g_b[r] * g_Xp[r * DD + d];
    atomicAdd(&g_Sbase[d], p);
}

// ---------------- edge_feats[c]: warp/edge, lane-parallel prefetch ----------
__global__ void k_edge(const int* __restrict__ rows) {
    int gw = (blockIdx.x * blockDim.x + threadIdx.x) >> 5;
    if (gw >= NE) return;
    int lane = threadIdx.x & 31;
    int s = g_col_ptr[gw], e = g_col_ptr[gw + 1];
    float4 acc = ((const float4*)g_Sbase)[lane];
    for (int j0 = s; j0 < e; j0 += 32) {
        int myj = j0 + lane;
        int rr = 0; float cf = 0.f;
        if (myj < e) {
            int k = g_col_ent[myj];
            rr = rows[k];
            cf = g_coef[k];
        }
        int cnt = min(32, e - j0);
        for (int t = 0; t < cnt; t++) {
            int r2 = __shfl_sync(0xffffffffu, rr, t);
            float c2 = __shfl_sync(0xffffffffu, cf, t);
            if (c2 != 0.f) {  // warp-uniform branch
                float4 xv = ((const float4*)(g_Xp + r2 * DD))[lane];
                acc.x += c2 * xv.x; acc.y += c2 * xv.y;
                acc.z += c2 * xv.z; acc.w += c2 * xv.w;
            }
        }
    }
    ((float4*)(g_ef + gw * DD))[lane] = acc;
}

// ---------------- out[r]: warp/row, lane-parallel prefetch ------------------
__global__ void k_out(const int* __restrict__ cols, const float* __restrict__ vals,
                      const float* __restrict__ bias, float* __restrict__ out) {
    int gw = (blockIdx.x * blockDim.x + threadIdx.x) >> 5;
    if (gw >= NN) return;
    int lane = threadIdx.x & 31;
    int s = g_row_ptr[gw], e = g_row_ptr[gw + 1];
    float4 acc = ((const float4*)bias)[lane];
    for (int j0 = s; j0 < e; j0 += 32) {
        int myj = j0 + lane;
        int cc = 0; float ww = 0.f;
        if (myj < e) {
            int k = g_row_ent[myj];
            cc = cols[k];
            ww = vals[k];
        }
        int cnt = min(32, e - j0);
        for (int t = 0; t < cnt; t++) {
            int c2 = __shfl_sync(0xffffffffu, cc, t);
            float w2 = __shfl_sync(0xffffffffu, ww, t);
            float4 ev = ((const float4*)(g_ef + c2 * DD))[lane];
            acc.x += w2 * ev.x; acc.y += w2 * ev.y;
            acc.z += w2 * ev.z; acc.w += w2 * ev.w;
        }
    }
    ((float4*)(out + gw * DD))[lane] = acc;
}

// ---------------- launcher ----------------
extern "C" void kernel_launch(void* const* d_in, const int* in_sizes, int n_in,
                              void* d_out, int out_size) {
    const float* x    = (const float*)d_in[0];
    const int*   rows = (const int*)d_in[1];
    const int*   cols = (const int*)d_in[2];
    const float* vals = (const float*)d_in[3];
    const float* W    = (const float*)d_in[4];
    const float* a    = (const float*)d_in[5];
    const float* bias = (const float*)d_in[6];
    float* out = (float*)d_out;

    k_zero<<<80, 256>>>();
    k_hist<<<(NZ / 4 + 255) / 256, 256>>>(rows, cols, vals);
    k_scan1<<<NBR + NBC, SB>>>();
    k_scan2<<<1, 64>>>();
    k_scan3<<<NBR + NBC, SB>>>();
    k_fill<<<(NZ / 4 + 255) / 256, 256>>>(rows, cols);
    k_gemm<<<(NN + BM - 1) / BM, 256>>>(x, W);
    k_e2<<<(NE * 32 + 255) / 256, 256>>>(rows, vals);
    k_yhat<<<(NN * 32 + 255) / 256, 256>>>(cols, vals, a);
    k_attn<<<(NN + 255) / 256, 256>>>(cols);
    k_sbase<<<(NN + 127) / 128, 128>>>();
    k_edge<<<(NE * 32 + 255) / 256, 256>>>(rows);
    k_out<<<(NN * 32 + 255) / 256, 256>>>(cols, vals, bias, out);
}